// round 3
// baseline (speedup 1.0000x reference)
#include <cuda_runtime.h>

// MemoryAugmentation: x[32,256,88,88] f32, mem[10,88,88] f32
//   score[b,c,m] = sum_hw x*mem ; softmax over m ; out[b,c,h,w] = sum_m score*mem
//
// Design: one 512-thread block per SM. mem staged through 155 KB of shared
// memory in 2 chunks; phase 2 iterates chunks in reverse so the chunk phase 1
// left in smem is reused (3 chunk loads total per block). Each warp owns <=4
// rows; lanes own strided float4 positions. Inner product uses packed
// fma.rn.f32x2 (FFMA2) on position pairs, halving FMA issue count.
//
// Register budget (TPB=512 -> 128-reg cap): m-OUTER loop ordering keeps the
// live set at acc[4][10] u64 (80) + xv[4] (16) + one transient mv (4) +
// addressing (~15) ~= 115 regs. Holding all 10 mv vectors live (m-inner)
// would need ~150 regs and spill.

constexpr int HW     = 88 * 88;       // 7744
constexpr int HW4    = HW / 4;        // 1936 float4 per row
constexpr int MS     = 10;            // memory slots
constexpr int ROWS   = 32 * 256;      // 8192 (b,c) rows
constexpr int NCHUNK = 2;
constexpr int CHUNK4 = HW4 / NCHUNK;  // 968 float4 per chunk per slot
constexpr int TPB    = 512;
constexpr int NWARP  = TPB / 32;      // 16
constexpr int MAX_RW = 4;             // rows per warp (needs grid >= 128)
constexpr int SMEM_BYTES = MS * CHUNK4 * 16;  // 154,880 B

using u64 = unsigned long long;

// Packed dual-FMA: d = a * b + d on two f32 lanes (sm_100+ FFMA2).
__device__ __forceinline__ void fma2(u64& d, u64 a, u64 b) {
    asm("fma.rn.f32x2 %0, %1, %2, %3;" : "=l"(d) : "l"(a), "l"(b), "l"(d));
}
__device__ __forceinline__ u64 pack2(float lo, float hi) {
    u64 r; asm("mov.b64 %0, {%1, %2};" : "=l"(r) : "f"(lo), "f"(hi)); return r;
}
__device__ __forceinline__ float2 unpack2(u64 v) {
    float2 r; asm("mov.b64 {%0, %1}, %2;" : "=f"(r.x), "=f"(r.y) : "l"(v));
    return r;
}

__global__ __launch_bounds__(TPB, 1)
void memaug_kernel(const float* __restrict__ x,
                   const float* __restrict__ memw,
                   float* __restrict__ out,
                   int total_warps)
{
    extern __shared__ ulonglong2 smem[];   // [MS][CHUNK4] packed float4
    const int tid  = threadIdx.x;
    const int lane = tid & 31;
    const int gw   = blockIdx.x * NWARP + (tid >> 5);

    // Rows owned by this warp (uniform across the warp).
    int nrows = 0;
    size_t rbase[MAX_RW];                  // row * HW4 (float4 index)
    #pragma unroll
    for (int i = 0; i < MAX_RW; i++) {
        int r = gw + i * total_warps;
        if (r < ROWS) { rbase[nrows] = (size_t)r * HW4; nrows++; }
    }

    // acc[r][m]: packed pair (even-position partial, odd-position partial).
    u64 acc[MAX_RW][MS];
    #pragma unroll
    for (int r = 0; r < MAX_RW; r++)
        #pragma unroll
        for (int m = 0; m < MS; m++) acc[r][m] = 0ull;   // (0.f, 0.f)

    const ulonglong2* __restrict__ x4 = reinterpret_cast<const ulonglong2*>(x);
    const ulonglong2* __restrict__ m4 = reinterpret_cast<const ulonglong2*>(memw);
    ulonglong2* __restrict__ o4       = reinterpret_cast<ulonglong2*>(out);

    // ---------------- Phase 1: score = X @ M^T (packed partials) ---------
    for (int c = 0; c < NCHUNK; c++) {
        if (c) __syncthreads();              // protect smem before overwrite
        #pragma unroll
        for (int m = 0; m < MS; m++)
            for (int j = tid; j < CHUNK4; j += TPB)
                smem[m * CHUNK4 + j] = m4[m * HW4 + c * CHUNK4 + j];
        __syncthreads();

        const size_t base = (size_t)c * CHUNK4;
        for (int p = lane; p < CHUNK4; p += 32) {
            // Front-batched independent x loads (MLP).
            ulonglong2 xv[MAX_RW];
            #pragma unroll
            for (int r = 0; r < MAX_RW; r++)
                if (r < nrows) xv[r] = x4[rbase[r] + base + p];
            // Stream mem vectors one slot at a time (m-outer: low reg use).
            #pragma unroll
            for (int m = 0; m < MS; m++) {
                ulonglong2 mv = smem[m * CHUNK4 + p];
                #pragma unroll
                for (int r = 0; r < MAX_RW; r++) {
                    if (r < nrows) {
                        fma2(acc[r][m], xv[r].x, mv.x);
                        fma2(acc[r][m], xv[r].y, mv.y);
                    }
                }
            }
        }
    }

    // ------------- warp reduce + softmax; repack scores ------------------
    #pragma unroll
    for (int r = 0; r < MAX_RW; r++) {
        if (r < nrows) {
            float sc[MS];
            #pragma unroll
            for (int m = 0; m < MS; m++) {
                float2 t = unpack2(acc[r][m]);
                float v = t.x + t.y;
                #pragma unroll
                for (int o = 16; o > 0; o >>= 1)
                    v += __shfl_xor_sync(0xffffffffu, v, o);
                sc[m] = v;                   // every lane holds the total
            }
            float mx = sc[0];
            #pragma unroll
            for (int m = 1; m < MS; m++) mx = fmaxf(mx, sc[m]);
            float s = 0.0f;
            #pragma unroll
            for (int m = 0; m < MS; m++) {
                float e = __expf(sc[m] - mx);
                sc[m] = e;
                s += e;
            }
            float inv = 1.0f / s;
            #pragma unroll
            for (int m = 0; m < MS; m++) {
                float w = sc[m] * inv;
                acc[r][m] = pack2(w, w);     // broadcast pair for phase 2
            }
        }
    }

    // ---------------- Phase 2: out = score @ M ----------------------------
    // Reverse chunk order: the last phase-1 chunk is still resident in smem.
    for (int cc = 0; cc < NCHUNK; cc++) {
        const int c = NCHUNK - 1 - cc;
        if (cc) {
            __syncthreads();
            #pragma unroll
            for (int m = 0; m < MS; m++)
                for (int j = tid; j < CHUNK4; j += TPB)
                    smem[m * CHUNK4 + j] = m4[m * HW4 + c * CHUNK4 + j];
            __syncthreads();
        }

        const size_t base = (size_t)c * CHUNK4;
        for (int p = lane; p < CHUNK4; p += 32) {
            u64 ox[MAX_RW], oy[MAX_RW];
            #pragma unroll
            for (int r = 0; r < MAX_RW; r++) { ox[r] = 0ull; oy[r] = 0ull; }
            #pragma unroll
            for (int m = 0; m < MS; m++) {
                ulonglong2 mv = smem[m * CHUNK4 + p];
                #pragma unroll
                for (int r = 0; r < MAX_RW; r++) {
                    if (r < nrows) {
                        fma2(ox[r], acc[r][m], mv.x);
                        fma2(oy[r], acc[r][m], mv.y);
                    }
                }
            }
            #pragma unroll
            for (int r = 0; r < MAX_RW; r++) {
                if (r < nrows) {
                    ulonglong2 ov; ov.x = ox[r]; ov.y = oy[r];
                    o4[rbase[r] + base + p] = ov;
                }
            }
        }
    }
}

extern "C" void kernel_launch(void* const* d_in, const int* in_sizes, int n_in,
                              void* d_out, int out_size)
{
    const float* x    = (const float*)d_in[0];
    const float* memw = (const float*)d_in[1];
    float* out        = (float*)d_out;

    int dev = 0;
    cudaGetDevice(&dev);
    int sms = 148;
    cudaDeviceGetAttribute(&sms, cudaDevAttrMultiProcessorCount, dev);
    int grid = (sms < 128) ? 128 : sms;   // MAX_RW=4 @16 warps needs >=128

    cudaFuncSetAttribute(memaug_kernel,
                         cudaFuncAttributeMaxDynamicSharedMemorySize,
                         SMEM_BYTES);
    memaug_kernel<<<grid, TPB, SMEM_BYTES>>>(x, memw, out, grid * NWARP);
}

// round 4
// speedup vs baseline: 1.0840x; 1.0840x over previous
#include <cuda_runtime.h>

// MemoryAugmentation: x[32,256,88,88] f32, mem[10,88,88] f32
//   score[b,c,m] = sum_hw x*mem ; softmax over m ; out[b,c,h,w] = sum_m score*mem
//
// R4 design (from R3 ncu: alu=43% addressing bloat, DRAM=37.9% MLP-limited):
//  * grid=128 x 16 warps x exactly 4 rows = 8192 rows -> zero predication
//  * uniform 30-tile main loop (32 float4/tile) + 8-lane tail -> no divergence
//  * byte pointers advanced by +512 -> no IMAD.WIDE address chains
//  * 2-stage ping-pong prefetch of x tiles -> LDGs overlap a full tile of
//    FMA work (effective MLP x2 -> DRAM toward 6 TB/s)
//  * packed fma.rn.f32x2 throughout (halved FMA issue count)
// mem staged via 155 KB smem in 2 chunks; phase 2 walks chunks in reverse to
// reuse the chunk phase 1 left resident (3 chunk loads per block total).

constexpr int HW     = 88 * 88;        // 7744
constexpr int HW4    = HW / 4;         // 1936 float4 per row
constexpr int MS     = 10;
constexpr int ROWS   = 32 * 256;       // 8192
constexpr int NCHUNK = 2;
constexpr int CHUNK4 = HW4 / NCHUNK;   // 968 float4 per chunk per slot
constexpr int TILES  = 30;             // 30*32 = 960 float4 main part
constexpr int TAIL   = CHUNK4 - TILES * 32;   // 8
constexpr int TPB    = 512;
constexpr int NWARP  = TPB / 32;       // 16
constexpr int GRID   = 128;
constexpr int TOTAL_WARPS = GRID * NWARP;     // 2048; ROWS = 4 * 2048 exactly
constexpr int RW     = 4;              // rows per warp (uniform)
constexpr int SLOT_STRIDE = CHUNK4 * 16;      // 15488 B per slot in smem
constexpr int SMEM_BYTES  = MS * SLOT_STRIDE; // 154880 B
constexpr int ROW_STRIDE_B = HW4 * 16;        // 30976 B per x row

using u64 = unsigned long long;

__device__ __forceinline__ void fma2(u64& d, u64 a, u64 b) {
    asm("fma.rn.f32x2 %0, %1, %2, %3;" : "=l"(d) : "l"(a), "l"(b), "l"(d));
}
__device__ __forceinline__ u64 pack2(float lo, float hi) {
    u64 r; asm("mov.b64 %0, {%1, %2};" : "=l"(r) : "f"(lo), "f"(hi)); return r;
}
__device__ __forceinline__ float2 unpack2(u64 v) {
    float2 r; asm("mov.b64 {%0, %1}, %2;" : "=f"(r.x), "=f"(r.y) : "l"(v));
    return r;
}

__global__ __launch_bounds__(TPB, 1)
void memaug_kernel(const float* __restrict__ x,
                   const float* __restrict__ memw,
                   float* __restrict__ out)
{
    extern __shared__ char smem[];     // [MS][CHUNK4] float4, slot-major
    const int tid  = threadIdx.x;
    const int lane = tid & 31;
    const int gw   = blockIdx.x * NWARP + (tid >> 5);

    // Every warp owns exactly RW=4 rows: gw, gw+2048, gw+4096, gw+6144.
    const char* const xc = (const char*)x;
    char* const oc       = (char*)out;

    u64 acc[RW][MS];
    #pragma unroll
    for (int r = 0; r < RW; r++)
        #pragma unroll
        for (int m = 0; m < MS; m++) acc[r][m] = 0ull;

    // ================= Phase 1: score = X @ M^T =========================
    for (int c = 0; c < NCHUNK; c++) {
        if (c) __syncthreads();
        {   // stage mem chunk into smem
            const ulonglong2* __restrict__ src =
                (const ulonglong2*)memw;
            ulonglong2* __restrict__ dst = (ulonglong2*)smem;
            #pragma unroll
            for (int m = 0; m < MS; m++)
                for (int j = tid; j < CHUNK4; j += TPB)
                    dst[m * CHUNK4 + j] = src[m * HW4 + c * CHUNK4 + j];
        }
        __syncthreads();

        // Per-row byte pointers at tile 0 of this chunk.
        const char* xp[RW];
        #pragma unroll
        for (int r = 0; r < RW; r++)
            xp[r] = xc + (size_t)(gw + r * TOTAL_WARPS) * ROW_STRIDE_B
                       + (size_t)c * (CHUNK4 * 16) + lane * 16;
        const char* sp = smem + lane * 16;

        ulonglong2 bA[RW], bB[RW];
        #pragma unroll
        for (int r = 0; r < RW; r++)
            bA[r] = *(const ulonglong2*)xp[r];       // tile 0

        #pragma unroll 1
        for (int t = 0; t < TILES; t += 2) {
            // prefetch tile t+1 (always exists: TILES even)
            #pragma unroll
            for (int r = 0; r < RW; r++) {
                xp[r] += 512;
                bB[r] = *(const ulonglong2*)xp[r];
            }
            // compute tile t with bA
            #pragma unroll
            for (int m = 0; m < MS; m++) {
                ulonglong2 mv = *(const ulonglong2*)(sp + m * SLOT_STRIDE);
                #pragma unroll
                for (int r = 0; r < RW; r++) {
                    fma2(acc[r][m], bA[r].x, mv.x);
                    fma2(acc[r][m], bA[r].y, mv.y);
                }
            }
            sp += 512;
            // prefetch tile t+2 (guard last)
            if (t + 2 < TILES) {
                #pragma unroll
                for (int r = 0; r < RW; r++) {
                    xp[r] += 512;
                    bA[r] = *(const ulonglong2*)xp[r];
                }
            } else {
                #pragma unroll
                for (int r = 0; r < RW; r++) xp[r] += 512;
            }
            // compute tile t+1 with bB
            #pragma unroll
            for (int m = 0; m < MS; m++) {
                ulonglong2 mv = *(const ulonglong2*)(sp + m * SLOT_STRIDE);
                #pragma unroll
                for (int r = 0; r < RW; r++) {
                    fma2(acc[r][m], bB[r].x, mv.x);
                    fma2(acc[r][m], bB[r].y, mv.y);
                }
            }
            sp += 512;
        }
        // tail: 8 float4 (lanes 0..7); xp/sp already point at tile TILES
        if (lane < TAIL) {
            ulonglong2 xv[RW];
            #pragma unroll
            for (int r = 0; r < RW; r++)
                xv[r] = *(const ulonglong2*)xp[r];
            #pragma unroll
            for (int m = 0; m < MS; m++) {
                ulonglong2 mv = *(const ulonglong2*)(sp + m * SLOT_STRIDE);
                #pragma unroll
                for (int r = 0; r < RW; r++) {
                    fma2(acc[r][m], xv[r].x, mv.x);
                    fma2(acc[r][m], xv[r].y, mv.y);
                }
            }
        }
    }

    // ============== warp reduce + softmax; repack scores ================
    #pragma unroll
    for (int r = 0; r < RW; r++) {
        float sc[MS];
        #pragma unroll
        for (int m = 0; m < MS; m++) {
            float2 t = unpack2(acc[r][m]);
            float v = t.x + t.y;
            #pragma unroll
            for (int o = 16; o > 0; o >>= 1)
                v += __shfl_xor_sync(0xffffffffu, v, o);
            sc[m] = v;                       // every lane holds the total
        }
        float mx = sc[0];
        #pragma unroll
        for (int m = 1; m < MS; m++) mx = fmaxf(mx, sc[m]);
        float s = 0.0f;
        #pragma unroll
        for (int m = 0; m < MS; m++) {
            float e = __expf(sc[m] - mx);
            sc[m] = e;
            s += e;
        }
        float inv = 1.0f / s;
        #pragma unroll
        for (int m = 0; m < MS; m++) {
            float w = sc[m] * inv;
            acc[r][m] = pack2(w, w);         // broadcast pair for phase 2
        }
    }

    // ================= Phase 2: out = score @ M =========================
    // Reverse chunk order: the last phase-1 chunk is still resident.
    for (int cc = 0; cc < NCHUNK; cc++) {
        const int c = NCHUNK - 1 - cc;
        if (cc) {
            __syncthreads();
            const ulonglong2* __restrict__ src = (const ulonglong2*)memw;
            ulonglong2* __restrict__ dst = (ulonglong2*)smem;
            #pragma unroll
            for (int m = 0; m < MS; m++)
                for (int j = tid; j < CHUNK4; j += TPB)
                    dst[m * CHUNK4 + j] = src[m * HW4 + c * CHUNK4 + j];
            __syncthreads();
        }

        char* op[RW];
        #pragma unroll
        for (int r = 0; r < RW; r++)
            op[r] = oc + (size_t)(gw + r * TOTAL_WARPS) * ROW_STRIDE_B
                       + (size_t)c * (CHUNK4 * 16) + lane * 16;
        const char* sp = smem + lane * 16;

        #pragma unroll 1
        for (int t = 0; t < TILES; t++) {
            u64 ox[RW], oy[RW];
            #pragma unroll
            for (int r = 0; r < RW; r++) { ox[r] = 0ull; oy[r] = 0ull; }
            #pragma unroll
            for (int m = 0; m < MS; m++) {
                ulonglong2 mv = *(const ulonglong2*)(sp + m * SLOT_STRIDE);
                #pragma unroll
                for (int r = 0; r < RW; r++) {
                    fma2(ox[r], acc[r][m], mv.x);
                    fma2(oy[r], acc[r][m], mv.y);
                }
            }
            #pragma unroll
            for (int r = 0; r < RW; r++) {
                ulonglong2 ov; ov.x = ox[r]; ov.y = oy[r];
                *(ulonglong2*)op[r] = ov;
                op[r] += 512;
            }
            sp += 512;
        }
        if (lane < TAIL) {
            u64 ox[RW], oy[RW];
            #pragma unroll
            for (int r = 0; r < RW; r++) { ox[r] = 0ull; oy[r] = 0ull; }
            #pragma unroll
            for (int m = 0; m < MS; m++) {
                ulonglong2 mv = *(const ulonglong2*)(sp + m * SLOT_STRIDE);
                #pragma unroll
                for (int r = 0; r < RW; r++) {
                    fma2(ox[r], acc[r][m], mv.x);
                    fma2(oy[r], acc[r][m], mv.y);
                }
            }
            #pragma unroll
            for (int r = 0; r < RW; r++) {
                ulonglong2 ov; ov.x = ox[r]; ov.y = oy[r];
                *(ulonglong2*)op[r] = ov;
            }
        }
    }
}

extern "C" void kernel_launch(void* const* d_in, const int* in_sizes, int n_in,
                              void* d_out, int out_size)
{
    const float* x    = (const float*)d_in[0];
    const float* memw = (const float*)d_in[1];
    float* out        = (float*)d_out;

    cudaFuncSetAttribute(memaug_kernel,
                         cudaFuncAttributeMaxDynamicSharedMemorySize,
                         SMEM_BYTES);
    memaug_kernel<<<GRID, TPB, SMEM_BYTES>>>(x, memw, out);
}

// round 13
// speedup vs baseline: 1.3637x; 1.2581x over previous
#include <cuda_runtime.h>

// MemoryAugmentation: x[32,256,88,88] f32, mem[10,88,88] f32
//   score[b,c,m] = sum_hw x*mem ; softmax over m ; out = sum_m score*mem
//
// R5 (from R4 ncu: ~1 DRAM latency exposed per tile; depth-1 prefetch was
// register-capped by 80-reg accumulators):
//  * fma.rn.f32x2 lanes repacked as (m, m+1) PAIRS -> acc[4][5] = 40 regs
//  * mem staged in smem pair-interleaved; lanes own scalars {l+32k} so the
//    pair reads are conflict-free LDS.64 (stride 8B)
//  * freed regs fund a DEPTH-3 register prefetch ring for x (the actual fix)
//  * grid=128 x 16 warps x 4 rows (uniform), NCHUNK=2, 155KB smem staging,
//    phase 2 walks chunks in reverse to reuse the resident chunk.

constexpr int HW     = 88 * 88;      // 7744 scalars per row
constexpr int HW4    = HW / 4;       // 1936 float4 per row
constexpr int MS     = 10;
constexpr int NPR    = 5;            // m-pairs
constexpr int ROWS   = 32 * 256;     // 8192
constexpr int NCHUNK = 2;
constexpr int CSCAL  = HW / NCHUNK;  // 3872 scalars per chunk
constexpr int CHUNK4 = HW4 / NCHUNK; // 968 float4 per chunk
constexpr int TILES  = 30;           // 30*128 = 3840 scalars; tail = 32
constexpr int TPB    = 512;
constexpr int NWARP  = 16;
constexpr int GRID   = 128;
constexpr int TOTW   = GRID * NWARP; // 2048 warps; ROWS = 4*2048 exactly
constexpr int RW     = 4;
constexpr int PSLOT  = CSCAL * 8;    // 30976 B per pair-slot in smem
constexpr int SMEM_BYTES = NPR * PSLOT;  // 154880 B

using u64 = unsigned long long;

__device__ __forceinline__ void fma2(u64& d, u64 a, u64 b) {
    asm("fma.rn.f32x2 %0, %1, %2, %3;" : "=l"(d) : "l"(a), "l"(b), "l"(d));
}
__device__ __forceinline__ u64 pack2(float lo, float hi) {
    u64 r; asm("mov.b64 %0, {%1, %2};" : "=l"(r) : "f"(lo), "f"(hi)); return r;
}
__device__ __forceinline__ float2 unpack2(u64 v) {
    float2 r; asm("mov.b64 {%0, %1}, %2;" : "=f"(r.x), "=f"(r.y) : "l"(v));
    return r;
}
__device__ __forceinline__ u64 lds64(const char* p) {
    return *reinterpret_cast<const u64*>(p);
}

__global__ __launch_bounds__(TPB, 1)
void memaug_kernel(const float* __restrict__ x,
                   const float* __restrict__ memw,
                   float* __restrict__ out)
{
    extern __shared__ char smem[];   // NPR pair-slots of PSLOT bytes
    const int tid  = threadIdx.x;
    const int lane = tid & 31;
    const int gw   = blockIdx.x * NWARP + (tid >> 5);

    // acc[r][pr] lanes = (partial_m=2pr, partial_m=2pr+1)
    u64 acc[RW][NPR];
    #pragma unroll
    for (int r = 0; r < RW; r++)
        #pragma unroll
        for (int pr = 0; pr < NPR; pr++) acc[r][pr] = 0ull;

    const float4* __restrict__ m4 = reinterpret_cast<const float4*>(memw);

    // ---- staging helper: pair-interleave chunk c of mem into smem -------
    auto stage = [&](int c) {
        #pragma unroll
        for (int pr = 0; pr < NPR; pr++) {
            for (int jj = tid; jj < CHUNK4; jj += TPB) {
                float4 e = m4[(2 * pr)     * HW4 + c * CHUNK4 + jj];
                float4 o = m4[(2 * pr + 1) * HW4 + c * CHUNK4 + jj];
                float4* dst = reinterpret_cast<float4*>(smem + pr * PSLOT + jj * 32);
                dst[0] = make_float4(e.x, o.x, e.y, o.y);
                dst[1] = make_float4(e.z, o.z, e.w, o.w);
            }
        }
    };

    // ================= Phase 1: score = X @ M^T ==========================
    for (int c = 0; c < NCHUNK; c++) {
        if (c) __syncthreads();
        stage(c);
        __syncthreads();

        const float* xq[RW];
        #pragma unroll
        for (int r = 0; r < RW; r++)
            xq[r] = x + (size_t)(gw + r * TOTW) * HW + c * CSCAL + lane;
        const char* sp = smem + lane * 8;

        // prefetch ring: 3 stages of 4 rows x 4 k-slices (LDG.32, coalesced)
        float xb0[RW][4], xb1[RW][4], xb2[RW][4];
        #pragma unroll
        for (int r = 0; r < RW; r++)
            #pragma unroll
            for (int k = 0; k < 4; k++) {
                xb0[r][k] = xq[r][0 * 128 + k * 32];
                xb1[r][k] = xq[r][1 * 128 + k * 32];
                xb2[r][k] = xq[r][2 * 128 + k * 32];
            }

#define P1_STEP(XB, DO_PF)                                                   \
        do {                                                                 \
            _Pragma("unroll")                                                \
            for (int h = 0; h < 2; h++) {                                    \
                u64 xd[RW][2];                                               \
                _Pragma("unroll")                                            \
                for (int r = 0; r < RW; r++) {                               \
                    xd[r][0] = pack2(XB[r][2 * h],     XB[r][2 * h]);        \
                    xd[r][1] = pack2(XB[r][2 * h + 1], XB[r][2 * h + 1]);    \
                }                                                            \
                _Pragma("unroll")                                            \
                for (int pr = 0; pr < NPR; pr++) {                           \
                    u64 m0 = lds64(sp + pr * PSLOT + (2 * h) * 256);         \
                    u64 m1 = lds64(sp + pr * PSLOT + (2 * h) * 256 + 256);   \
                    _Pragma("unroll")                                        \
                    for (int r = 0; r < RW; r++) {                           \
                        fma2(acc[r][pr], xd[r][0], m0);                      \
                        fma2(acc[r][pr], xd[r][1], m1);                      \
                    }                                                        \
                }                                                            \
            }                                                                \
            if (DO_PF) {                                                     \
                _Pragma("unroll")                                            \
                for (int r = 0; r < RW; r++)                                 \
                    _Pragma("unroll")                                        \
                    for (int k = 0; k < 4; k++)                              \
                        XB[r][k] = xq[r][384 + k * 32];                      \
            }                                                                \
            _Pragma("unroll")                                                \
            for (int r = 0; r < RW; r++) xq[r] += 128;                       \
            sp += 1024;                                                      \
        } while (0)

        #pragma unroll 1
        for (int g = 0; g < TILES / 3 - 1; g++) {   // tiles 0..26, pf 3..29
            P1_STEP(xb0, true);
            P1_STEP(xb1, true);
            P1_STEP(xb2, true);
        }
        P1_STEP(xb0, false);                        // tiles 27..29
        P1_STEP(xb1, false);
        P1_STEP(xb2, false);
#undef P1_STEP

        {   // tail: 32 scalars = one k-slice, all lanes active
            u64 xd[RW];
            #pragma unroll
            for (int r = 0; r < RW; r++) {
                float xv = xq[r][0];
                xd[r] = pack2(xv, xv);
            }
            #pragma unroll
            for (int pr = 0; pr < NPR; pr++) {
                u64 m0 = lds64(sp + pr * PSLOT);
                #pragma unroll
                for (int r = 0; r < RW; r++) fma2(acc[r][pr], xd[r], m0);
            }
        }
    }

    // ============== warp reduce + softmax; repack weights ================
    #pragma unroll
    for (int r = 0; r < RW; r++) {
        float sc[MS];
        #pragma unroll
        for (int pr = 0; pr < NPR; pr++) {
            float2 t = unpack2(acc[r][pr]);
            sc[2 * pr]     = t.x;
            sc[2 * pr + 1] = t.y;
        }
        #pragma unroll
        for (int m = 0; m < MS; m++) {
            float v = sc[m];
            #pragma unroll
            for (int o = 16; o > 0; o >>= 1)
                v += __shfl_xor_sync(0xffffffffu, v, o);
            sc[m] = v;                       // every lane holds the total
        }
        float mx = sc[0];
        #pragma unroll
        for (int m = 1; m < MS; m++) mx = fmaxf(mx, sc[m]);
        float s = 0.0f;
        #pragma unroll
        for (int m = 0; m < MS; m++) {
            float e = __expf(sc[m] - mx);
            sc[m] = e;
            s += e;
        }
        float inv = 1.0f / s;
        #pragma unroll
        for (int pr = 0; pr < NPR; pr++)
            acc[r][pr] = pack2(sc[2 * pr] * inv, sc[2 * pr + 1] * inv);
    }

    // ================= Phase 2: out = score @ M ==========================
    // Reverse chunk order: chunk (NCHUNK-1) is still resident in smem.
    for (int cc = 0; cc < NCHUNK; cc++) {
        const int c = NCHUNK - 1 - cc;
        if (cc) {
            __syncthreads();
            stage(c);
            __syncthreads();
        }

        float* op[RW];
        #pragma unroll
        for (int r = 0; r < RW; r++)
            op[r] = out + (size_t)(gw + r * TOTW) * HW + c * CSCAL + lane;
        const char* sp = smem + lane * 8;

        #pragma unroll 1
        for (int t = 0; t < TILES; t++) {
            u64 o[RW][4];
            #pragma unroll
            for (int r = 0; r < RW; r++)
                #pragma unroll
                for (int k = 0; k < 4; k++) o[r][k] = 0ull;
            #pragma unroll
            for (int pr = 0; pr < NPR; pr++) {
                u64 m0 = lds64(sp + pr * PSLOT + 0 * 256);
                u64 m1 = lds64(sp + pr * PSLOT + 1 * 256);
                u64 m2 = lds64(sp + pr * PSLOT + 2 * 256);
                u64 m3 = lds64(sp + pr * PSLOT + 3 * 256);
                #pragma unroll
                for (int r = 0; r < RW; r++) {
                    fma2(o[r][0], acc[r][pr], m0);
                    fma2(o[r][1], acc[r][pr], m1);
                    fma2(o[r][2], acc[r][pr], m2);
                    fma2(o[r][3], acc[r][pr], m3);
                }
            }
            #pragma unroll
            for (int r = 0; r < RW; r++) {
                #pragma unroll
                for (int k = 0; k < 4; k++) {
                    float2 v = unpack2(o[r][k]);
                    op[r][k * 32] = v.x + v.y;
                }
                op[r] += 128;
            }
            sp += 1024;
        }
        {   // tail: one scalar per lane per row
            u64 o2[RW];
            #pragma unroll
            for (int r = 0; r < RW; r++) o2[r] = 0ull;
            #pragma unroll
            for (int pr = 0; pr < NPR; pr++) {
                u64 m0 = lds64(sp + pr * PSLOT);
                #pragma unroll
                for (int r = 0; r < RW; r++) fma2(o2[r], acc[r][pr], m0);
            }
            #pragma unroll
            for (int r = 0; r < RW; r++) {
                float2 v = unpack2(o2[r]);
                op[r][0] = v.x + v.y;
            }
        }
    }
}

extern "C" void kernel_launch(void* const* d_in, const int* in_sizes, int n_in,
                              void* d_out, int out_size)
{
    const float* x    = (const float*)d_in[0];
    const float* memw = (const float*)d_in[1];
    float* out        = (float*)d_out;

    cudaFuncSetAttribute(memaug_kernel,
                         cudaFuncAttributeMaxDynamicSharedMemorySize,
                         SMEM_BYTES);
    memaug_kernel<<<GRID, TPB, SMEM_BYTES>>>(x, memw, out);
}

// round 14
// speedup vs baseline: 1.4164x; 1.0386x over previous
#include <cuda_runtime.h>

// MemoryAugmentation: x[32,256,88,88] f32, mem[10,88,88] f32
//   score[b,c,m] = sum_hw x*mem ; softmax over m ; out = sum_m score*mem
//
// R14 (from R13 ncu: regs=128 == cap -> depth-3 ring likely spilled; dur
// 112.7us, DRAM 54%): identical design but DEPTH-2 prefetch ring. 2 tiles
// of flight time (~3300 cyc) still covers DRAM latency (~600); freed regs
// (est. ~105 total) eliminate spills and give ptxas room to hoist LDS.
//  * fma.rn.f32x2 lanes = (m, m+1) pairs -> acc[4][5] = 40 regs
//  * mem pair-interleaved in smem; conflict-free LDS.64 (lane stride 8B)
//  * grid=128 x 16 warps x 4 rows uniform; NCHUNK=2; 155KB smem staging;
//    phase 2 walks chunks in reverse to reuse the resident chunk.

constexpr int HW     = 88 * 88;      // 7744 scalars per row
constexpr int HW4    = HW / 4;       // 1936 float4 per row
constexpr int MS     = 10;
constexpr int NPR    = 5;            // m-pairs
constexpr int ROWS   = 32 * 256;     // 8192
constexpr int NCHUNK = 2;
constexpr int CSCAL  = HW / NCHUNK;  // 3872 scalars per chunk
constexpr int CHUNK4 = HW4 / NCHUNK; // 968 float4 per chunk
constexpr int TILES  = 30;           // 30*128 = 3840 scalars; tail = 32
constexpr int TPB    = 512;
constexpr int NWARP  = 16;
constexpr int GRID   = 128;
constexpr int TOTW   = GRID * NWARP; // 2048 warps; ROWS = 4*2048 exactly
constexpr int RW     = 4;
constexpr int PSLOT  = CSCAL * 8;    // 30976 B per pair-slot in smem
constexpr int SMEM_BYTES = NPR * PSLOT;  // 154880 B

using u64 = unsigned long long;

__device__ __forceinline__ void fma2(u64& d, u64 a, u64 b) {
    asm("fma.rn.f32x2 %0, %1, %2, %3;" : "=l"(d) : "l"(a), "l"(b), "l"(d));
}
__device__ __forceinline__ u64 pack2(float lo, float hi) {
    u64 r; asm("mov.b64 %0, {%1, %2};" : "=l"(r) : "f"(lo), "f"(hi)); return r;
}
__device__ __forceinline__ float2 unpack2(u64 v) {
    float2 r; asm("mov.b64 {%0, %1}, %2;" : "=f"(r.x), "=f"(r.y) : "l"(v));
    return r;
}
__device__ __forceinline__ u64 lds64(const char* p) {
    return *reinterpret_cast<const u64*>(p);
}

__global__ __launch_bounds__(TPB, 1)
void memaug_kernel(const float* __restrict__ x,
                   const float* __restrict__ memw,
                   float* __restrict__ out)
{
    extern __shared__ char smem[];   // NPR pair-slots of PSLOT bytes
    const int tid  = threadIdx.x;
    const int lane = tid & 31;
    const int gw   = blockIdx.x * NWARP + (tid >> 5);

    // acc[r][pr] lanes = (partial_m=2pr, partial_m=2pr+1)
    u64 acc[RW][NPR];
    #pragma unroll
    for (int r = 0; r < RW; r++)
        #pragma unroll
        for (int pr = 0; pr < NPR; pr++) acc[r][pr] = 0ull;

    const float4* __restrict__ m4 = reinterpret_cast<const float4*>(memw);

    // ---- staging helper: pair-interleave chunk c of mem into smem -------
    auto stage = [&](int c) {
        #pragma unroll
        for (int pr = 0; pr < NPR; pr++) {
            for (int jj = tid; jj < CHUNK4; jj += TPB) {
                float4 e = m4[(2 * pr)     * HW4 + c * CHUNK4 + jj];
                float4 o = m4[(2 * pr + 1) * HW4 + c * CHUNK4 + jj];
                float4* dst = reinterpret_cast<float4*>(smem + pr * PSLOT + jj * 32);
                dst[0] = make_float4(e.x, o.x, e.y, o.y);
                dst[1] = make_float4(e.z, o.z, e.w, o.w);
            }
        }
    };

    // ================= Phase 1: score = X @ M^T ==========================
    for (int c = 0; c < NCHUNK; c++) {
        if (c) __syncthreads();
        stage(c);
        __syncthreads();

        const float* xq[RW];
        #pragma unroll
        for (int r = 0; r < RW; r++)
            xq[r] = x + (size_t)(gw + r * TOTW) * HW + c * CSCAL + lane;
        const char* sp = smem + lane * 8;

        // prefetch ring: 2 stages of 4 rows x 4 k-slices (LDG.32, coalesced)
        float xb0[RW][4], xb1[RW][4];
        #pragma unroll
        for (int r = 0; r < RW; r++)
            #pragma unroll
            for (int k = 0; k < 4; k++) {
                xb0[r][k] = xq[r][0 * 128 + k * 32];
                xb1[r][k] = xq[r][1 * 128 + k * 32];
            }

#define P1_STEP(XB, DO_PF)                                                   \
        do {                                                                 \
            _Pragma("unroll")                                                \
            for (int h = 0; h < 2; h++) {                                    \
                u64 xd[RW][2];                                               \
                _Pragma("unroll")                                            \
                for (int r = 0; r < RW; r++) {                               \
                    xd[r][0] = pack2(XB[r][2 * h],     XB[r][2 * h]);        \
                    xd[r][1] = pack2(XB[r][2 * h + 1], XB[r][2 * h + 1]);    \
                }                                                            \
                _Pragma("unroll")                                            \
                for (int pr = 0; pr < NPR; pr++) {                           \
                    u64 m0 = lds64(sp + pr * PSLOT + (2 * h) * 256);         \
                    u64 m1 = lds64(sp + pr * PSLOT + (2 * h) * 256 + 256);   \
                    _Pragma("unroll")                                        \
                    for (int r = 0; r < RW; r++) {                           \
                        fma2(acc[r][pr], xd[r][0], m0);                      \
                        fma2(acc[r][pr], xd[r][1], m1);                      \
                    }                                                        \
                }                                                            \
            }                                                                \
            if (DO_PF) {                                                     \
                _Pragma("unroll")                                            \
                for (int r = 0; r < RW; r++)                                 \
                    _Pragma("unroll")                                        \
                    for (int k = 0; k < 4; k++)                              \
                        XB[r][k] = xq[r][256 + k * 32];                      \
            }                                                                \
            _Pragma("unroll")                                                \
            for (int r = 0; r < RW; r++) xq[r] += 128;                       \
            sp += 1024;                                                      \
        } while (0)

        #pragma unroll 1
        for (int g = 0; g < TILES / 2 - 1; g++) {   // tiles 0..27, pf 2..29
            P1_STEP(xb0, true);
            P1_STEP(xb1, true);
        }
        P1_STEP(xb0, false);                        // tile 28
        P1_STEP(xb1, false);                        // tile 29
#undef P1_STEP

        {   // tail: 32 scalars = one k-slice, all lanes active
            u64 xd[RW];
            #pragma unroll
            for (int r = 0; r < RW; r++) {
                float xv = xq[r][0];
                xd[r] = pack2(xv, xv);
            }
            #pragma unroll
            for (int pr = 0; pr < NPR; pr++) {
                u64 m0 = lds64(sp + pr * PSLOT);
                #pragma unroll
                for (int r = 0; r < RW; r++) fma2(acc[r][pr], xd[r], m0);
            }
        }
    }

    // ============== warp reduce + softmax; repack weights ================
    #pragma unroll
    for (int r = 0; r < RW; r++) {
        float sc[MS];
        #pragma unroll
        for (int pr = 0; pr < NPR; pr++) {
            float2 t = unpack2(acc[r][pr]);
            sc[2 * pr]     = t.x;
            sc[2 * pr + 1] = t.y;
        }
        #pragma unroll
        for (int m = 0; m < MS; m++) {
            float v = sc[m];
            #pragma unroll
            for (int o = 16; o > 0; o >>= 1)
                v += __shfl_xor_sync(0xffffffffu, v, o);
            sc[m] = v;                       // every lane holds the total
        }
        float mx = sc[0];
        #pragma unroll
        for (int m = 1; m < MS; m++) mx = fmaxf(mx, sc[m]);
        float s = 0.0f;
        #pragma unroll
        for (int m = 0; m < MS; m++) {
            float e = __expf(sc[m] - mx);
            sc[m] = e;
            s += e;
        }
        float inv = 1.0f / s;
        #pragma unroll
        for (int pr = 0; pr < NPR; pr++)
            acc[r][pr] = pack2(sc[2 * pr] * inv, sc[2 * pr + 1] * inv);
    }

    // ================= Phase 2: out = score @ M ==========================
    // Reverse chunk order: chunk (NCHUNK-1) is still resident in smem.
    for (int cc = 0; cc < NCHUNK; cc++) {
        const int c = NCHUNK - 1 - cc;
        if (cc) {
            __syncthreads();
            stage(c);
            __syncthreads();
        }

        float* op[RW];
        #pragma unroll
        for (int r = 0; r < RW; r++)
            op[r] = out + (size_t)(gw + r * TOTW) * HW + c * CSCAL + lane;
        const char* sp = smem + lane * 8;

        #pragma unroll 1
        for (int t = 0; t < TILES; t++) {
            u64 o[RW][4];
            #pragma unroll
            for (int r = 0; r < RW; r++)
                #pragma unroll
                for (int k = 0; k < 4; k++) o[r][k] = 0ull;
            #pragma unroll
            for (int pr = 0; pr < NPR; pr++) {
                u64 m0 = lds64(sp + pr * PSLOT + 0 * 256);
                u64 m1 = lds64(sp + pr * PSLOT + 1 * 256);
                u64 m2 = lds64(sp + pr * PSLOT + 2 * 256);
                u64 m3 = lds64(sp + pr * PSLOT + 3 * 256);
                #pragma unroll
                for (int r = 0; r < RW; r++) {
                    fma2(o[r][0], acc[r][pr], m0);
                    fma2(o[r][1], acc[r][pr], m1);
                    fma2(o[r][2], acc[r][pr], m2);
                    fma2(o[r][3], acc[r][pr], m3);
                }
            }
            #pragma unroll
            for (int r = 0; r < RW; r++) {
                #pragma unroll
                for (int k = 0; k < 4; k++) {
                    float2 v = unpack2(o[r][k]);
                    op[r][k * 32] = v.x + v.y;
                }
                op[r] += 128;
            }
            sp += 1024;
        }
        {   // tail: one scalar per lane per row
            u64 o2[RW];
            #pragma unroll
            for (int r = 0; r < RW; r++) o2[r] = 0ull;
            #pragma unroll
            for (int pr = 0; pr < NPR; pr++) {
                u64 m0 = lds64(sp + pr * PSLOT);
                #pragma unroll
                for (int r = 0; r < RW; r++) fma2(o2[r], acc[r][pr], m0);
            }
            #pragma unroll
            for (int r = 0; r < RW; r++) {
                float2 v = unpack2(o2[r]);
                op[r][0] = v.x + v.y;
            }
        }
    }
}

extern "C" void kernel_launch(void* const* d_in, const int* in_sizes, int n_in,
                              void* d_out, int out_size)
{
    const float* x    = (const float*)d_in[0];
    const float* memw = (const float*)d_in[1];
    float* out        = (float*)d_out;

    cudaFuncSetAttribute(memaug_kernel,
                         cudaFuncAttributeMaxDynamicSharedMemorySize,
                         SMEM_BYTES);
    memaug_kernel<<<GRID, TPB, SMEM_BYTES>>>(x, memw, out);
}